// round 5
// baseline (speedup 1.0000x reference)
#include <cuda_runtime.h>
#include <cuda_fp16.h>

#define N_NODES 100000
#define N_EDGES 3200000
#define IN_CH 32
#define HID 16
#define SCAN_B 512
#define NB ((N_NODES + SCAN_B - 1) / SCAN_B)   // 196

// ---------------- device scratch (no allocs allowed) ----------------
__device__ __half2 g_p1h[N_NODES][8];   // x @ Wl1.T  (fp16, 32B/row)
__device__ float g_r1[N_NODES][HID];    // x @ Wr1.T
__device__ float g_p2[N_NODES];         // h @ Wl2.T
__device__ float g_r2[N_NODES];         // h @ Wr2.T
__device__ int   g_cnt[N_NODES];        // in-degree histogram
__device__ int   g_rowptr[N_NODES + 1]; // CSR row pointers (by dst)
__device__ int   g_woff[N_NODES];       // scatter write cursors
__device__ int   g_bsum[NB];            // scan block sums
__device__ int   g_srcs[N_EDGES];       // src ids bucketed by dst
__device__ int   g_idx64;               // 1 if edge_index is int64

// ---------------- K1: detect dtype + zero histogram ----------------
__global__ void init_kernel(const int* __restrict__ ei32) {
    int i = blockIdx.x * blockDim.x + threadIdx.x;
    if (i < N_NODES) g_cnt[i] = 0;
    if (blockIdx.x == 0) {
        __shared__ int s_or;
        if (threadIdx.x == 0) s_or = 0;
        __syncthreads();
        if (ei32[2 * threadIdx.x + 1] != 0) atomicOr(&s_or, 1);
        __syncthreads();
        if (threadIdx.x == 0) g_idx64 = (s_or == 0) ? 1 : 0;
    }
}

// ---------------- edge loads ----------------
__device__ __forceinline__ void load_edge(const void* ei, int e, int& s, int& d) {
    if (g_idx64) {
        const long long* p = (const long long*)ei;
        s = (int)__ldg(&p[e]);
        d = (int)__ldg(&p[N_EDGES + e]);
    } else {
        const int* p = (const int*)ei;
        s = __ldg(&p[e]);
        d = __ldg(&p[N_EDGES + e]);
    }
}

__device__ __forceinline__ int load_dst(const void* ei, int e) {
    if (g_idx64) return (int)__ldg(&((const long long*)ei)[N_EDGES + e]);
    return __ldg(&((const int*)ei)[N_EDGES + e]);
}

// ---------------- K2: histogram (blocks [0,EG)) + proj1 (blocks [EG,..)) --
#define EG ((N_EDGES + 255) / 256)   // 12500
#define NG ((N_NODES + 255) / 256)   // 391

__global__ void __launch_bounds__(256) histproj_kernel(
        const void* __restrict__ ei,
        const float* __restrict__ x,
        const float* __restrict__ Wl1,
        const float* __restrict__ Wr1) {
    if (blockIdx.x < EG) {
        int e = blockIdx.x * 256 + threadIdx.x;
        if (e < N_EDGES) atomicAdd(&g_cnt[load_dst(ei, e)], 1);
        return;
    }
    // ---- proj1: p1 = x@Wl1.T (fp16), r1 = x@Wr1.T (fp32) ----
    __shared__ float sWl[HID * IN_CH];
    __shared__ float sWr[HID * IN_CH];
    for (int t = threadIdx.x; t < HID * IN_CH; t += 256) {
        sWl[t] = Wl1[t];
        sWr[t] = Wr1[t];
    }
    __syncthreads();
    int i = (blockIdx.x - EG) * 256 + threadIdx.x;
    if (i >= N_NODES) return;

    float xr[IN_CH];
    const float4* xp = reinterpret_cast<const float4*>(x + (size_t)i * IN_CH);
#pragma unroll
    for (int j = 0; j < IN_CH / 4; j++) {
        float4 v = __ldg(&xp[j]);
        xr[4 * j + 0] = v.x; xr[4 * j + 1] = v.y;
        xr[4 * j + 2] = v.z; xr[4 * j + 3] = v.w;
    }
    float pl[HID];
#pragma unroll
    for (int k = 0; k < HID; k++) {
        float a = 0.0f, b = 0.0f;
#pragma unroll
        for (int j = 0; j < IN_CH; j++) {
            a = fmaf(xr[j], sWl[k * IN_CH + j], a);
            b = fmaf(xr[j], sWr[k * IN_CH + j], b);
        }
        pl[k] = a;
        g_r1[i][k] = b;
    }
#pragma unroll
    for (int j = 0; j < 8; j++)
        g_p1h[i][j] = __floats2half2_rn(pl[2 * j], pl[2 * j + 1]);
}

// ---------------- K3-K5: shuffle-based scan of g_cnt -> g_rowptr ----------
__global__ void scanA_kernel() {
    int t = blockIdx.x * SCAN_B + threadIdx.x;
    int v = (t < N_NODES) ? g_cnt[t] : 0;
    int lane = threadIdx.x & 31, wid = threadIdx.x >> 5;
    int sv = v;
#pragma unroll
    for (int off = 1; off < 32; off <<= 1) {
        int n = __shfl_up_sync(0xffffffffu, sv, off);
        if (lane >= off) sv += n;
    }
    __shared__ int wsum[16];
    if (lane == 31) wsum[wid] = sv;
    __syncthreads();
    if (wid == 0 && lane < 16) {
        int w = wsum[lane], sw = w;
#pragma unroll
        for (int off = 1; off < 16; off <<= 1) {
            int n = __shfl_up_sync(0xffffu, sw, off);
            if (lane >= off) sw += n;
        }
        wsum[lane] = sw - w;  // exclusive
    }
    __syncthreads();
    int excl = sv - v + wsum[wid];
    if (t < N_NODES) g_rowptr[t] = excl;
    if (threadIdx.x == SCAN_B - 1) g_bsum[blockIdx.x] = excl + v;
}

__global__ void scanB_kernel() {
    int v = (threadIdx.x < NB) ? g_bsum[threadIdx.x] : 0;
    int lane = threadIdx.x & 31, wid = threadIdx.x >> 5;
    int sv = v;
#pragma unroll
    for (int off = 1; off < 32; off <<= 1) {
        int n = __shfl_up_sync(0xffffffffu, sv, off);
        if (lane >= off) sv += n;
    }
    __shared__ int wsum[8];
    if (lane == 31) wsum[wid] = sv;
    __syncthreads();
    if (wid == 0 && lane < 8) {
        int w = wsum[lane], sw = w;
#pragma unroll
        for (int off = 1; off < 8; off <<= 1) {
            int n = __shfl_up_sync(0xffu, sw, off);
            if (lane >= off) sw += n;
        }
        wsum[lane] = sw - w;
    }
    __syncthreads();
    if (threadIdx.x < NB) g_bsum[threadIdx.x] = sv - v + wsum[wid];  // exclusive
}

__global__ void scanC_kernel() {
    int t = blockIdx.x * blockDim.x + threadIdx.x;
    if (t < N_NODES) {
        int r = g_rowptr[t] + g_bsum[t / SCAN_B];
        g_rowptr[t] = r;
        g_woff[t] = r;
    }
    if (t == 0) g_rowptr[N_NODES] = N_EDGES;
}

// ---------------- K6: scatter src ids into CSR buckets ----------------
__global__ void __launch_bounds__(256) scatter_kernel(const void* __restrict__ ei) {
    int e = blockIdx.x * blockDim.x + threadIdx.x;
    if (e >= N_EDGES) return;
    int s, d;
    load_edge(ei, e, s, d);
    int pos = atomicAdd(&g_woff[d], 1);
    g_srcs[pos] = s;
}

// ---------------- K7: gather layer 1 (fp16 p1, 4 edges in flight) --------
// One warp per node. Lane layout: group g = lane>>3 (4 groups, one edge
// each), c = lane&7 (half2 channel pair). 8 lanes read one 32B p1h row.
__global__ void __launch_bounds__(256) gather1_kernel(
        const float* __restrict__ b1,
        const float* __restrict__ Wl2,
        const float* __restrict__ Wr2) {
    int warp = (blockIdx.x * blockDim.x + threadIdx.x) >> 5;
    int lane = threadIdx.x & 31;
    if (warp >= N_NODES) return;
    int node = warp;
    int start = __ldg(&g_rowptr[node]);
    int end = __ldg(&g_rowptr[node + 1]);
    int g = lane >> 3;
    int c = lane & 7;

    float ax = 0.0f, ay = 0.0f;
    for (int e = start + g; e < end; e += 4) {
        int s = __ldg(&g_srcs[e]);
        float2 f = __half22float2(g_p1h[s][c]);
        ax += f.x;
        ay += f.y;
    }
    // fold 4 groups -> lanes 0-7
    ax += __shfl_down_sync(0xffffffffu, ax, 16);
    ay += __shfl_down_sync(0xffffffffu, ay, 16);
    ax += __shfl_down_sync(0xffffffffu, ax, 8);
    ay += __shfl_down_sync(0xffffffffu, ay, 8);

    float dinv = 1.0f / fmaxf((float)(end - start), 1.0f);
    float2 b = __ldg(&((const float2*)b1)[c]);
    float2 r = *((const float2*)g_r1[node] + c);
    float h0 = fmaxf(fmaf(ax, dinv, b.x + r.x), 0.0f);
    float h1 = fmaxf(fmaf(ay, dinv, b.y + r.y), 0.0f);
    float2 wl = __ldg(&((const float2*)Wl2)[c]);
    float2 wr = __ldg(&((const float2*)Wr2)[c]);
    float p2 = h0 * wl.x + h1 * wl.y;
    float r2 = h0 * wr.x + h1 * wr.y;
#pragma unroll
    for (int o = 4; o; o >>= 1) {
        p2 += __shfl_down_sync(0xffffffffu, p2, o);
        r2 += __shfl_down_sync(0xffffffffu, r2, o);
    }
    if (lane == 0) {
        g_p2[node] = p2;
        g_r2[node] = r2;
    }
}

// ---------------- K8: gather layer 2 (fused final epilogue) ----------------
__global__ void __launch_bounds__(256) gather2_kernel(
        const float* __restrict__ b2,
        float* __restrict__ out) {
    int warp = (blockIdx.x * blockDim.x + threadIdx.x) >> 5;
    int lane = threadIdx.x & 31;
    if (warp >= N_NODES) return;
    int start = __ldg(&g_rowptr[warp]);
    int end = __ldg(&g_rowptr[warp + 1]);
    float acc = 0.0f;
    for (int e = start + lane; e < end; e += 32)
        acc += __ldg(&g_p2[__ldg(&g_srcs[e])]);
#pragma unroll
    for (int o = 16; o; o >>= 1)
        acc += __shfl_down_sync(0xffffffffu, acc, o);
    if (lane == 0) {
        float dinv = 1.0f / fmaxf((float)(end - start), 1.0f);
        out[warp] = fmaf(acc, dinv, __ldg(&b2[0]) + g_r2[warp]);
    }
}

// ---------------- launch ----------------
extern "C" void kernel_launch(void* const* d_in, const int* in_sizes, int n_in,
                              void* d_out, int out_size) {
    const float* x   = (const float*)d_in[0];
    const void*  ei  = d_in[1];
    const float* Wl1 = (const float*)d_in[2];
    const float* Wr1 = (const float*)d_in[3];
    const float* b1  = (const float*)d_in[4];
    const float* Wl2 = (const float*)d_in[5];
    const float* Wr2 = (const float*)d_in[6];
    const float* b2  = (const float*)d_in[7];
    float* out = (float*)d_out;

    const int T = 256;
    const int WG = (N_NODES * 32 + T - 1) / T;  // 12500 (warp per node)

    init_kernel<<<NG, T>>>((const int*)ei);
    histproj_kernel<<<EG + NG, T>>>(ei, x, Wl1, Wr1);
    scanA_kernel<<<NB, SCAN_B>>>();
    scanB_kernel<<<1, 256>>>();
    scanC_kernel<<<NG, T>>>();
    scatter_kernel<<<EG, T>>>(ei);
    gather1_kernel<<<WG, T>>>(b1, Wl2, Wr2);
    gather2_kernel<<<WG, T>>>(b2, out);
}

// round 6
// speedup vs baseline: 1.2782x; 1.2782x over previous
#include <cuda_runtime.h>
#include <cuda_fp16.h>

#define N_NODES 100000
#define N_EDGES 3200000
#define IN_CH 32
#define HID 16
#define SCAN_B 512
#define NB ((N_NODES + SCAN_B - 1) / SCAN_B)   // 196
#define EG ((N_EDGES + 255) / 256)   // 12500
#define NG ((N_NODES + 255) / 256)   // 391

// ---------------- device scratch (no allocs allowed) ----------------
__device__ __half2 g_p1h[N_NODES][8];   // x @ Wl1.T  (fp16, 32B/row)
__device__ float g_r1[N_NODES][HID];    // x @ Wr1.T
__device__ float g_p2[N_NODES];         // h @ Wl2.T
__device__ float g_r2[N_NODES];         // h @ Wr2.T
__device__ int   g_cnt[N_NODES];        // in-degree histogram
__device__ int   g_rowptr[N_NODES + 1]; // CSR row pointers (by dst)
__device__ int   g_woff[N_NODES];       // scatter write cursors
__device__ int   g_bsum[NB];            // scan block sums
__device__ int   g_srcs[N_EDGES];       // src ids bucketed by dst
__device__ int   g_idx64;               // 1 if edge_index is int64

// ---------------- K1: detect dtype + zero histogram ----------------
__global__ void init_kernel(const int* __restrict__ ei32) {
    int i = blockIdx.x * blockDim.x + threadIdx.x;
    if (i < N_NODES) g_cnt[i] = 0;
    if (blockIdx.x == 0) {
        __shared__ int s_or;
        if (threadIdx.x == 0) s_or = 0;
        __syncthreads();
        if (ei32[2 * threadIdx.x + 1] != 0) atomicOr(&s_or, 1);
        __syncthreads();
        if (threadIdx.x == 0) g_idx64 = (s_or == 0) ? 1 : 0;
    }
}

// ---------------- edge loads ----------------
__device__ __forceinline__ void load_edge(const void* ei, int e, int& s, int& d) {
    if (g_idx64) {
        const long long* p = (const long long*)ei;
        s = (int)__ldg(&p[e]);
        d = (int)__ldg(&p[N_EDGES + e]);
    } else {
        const int* p = (const int*)ei;
        s = __ldg(&p[e]);
        d = __ldg(&p[N_EDGES + e]);
    }
}

__device__ __forceinline__ int load_dst(const void* ei, int e) {
    if (g_idx64) return (int)__ldg(&((const long long*)ei)[N_EDGES + e]);
    return __ldg(&((const int*)ei)[N_EDGES + e]);
}

// ---------------- K2: histogram ----------------
__global__ void __launch_bounds__(256) hist_kernel(const void* __restrict__ ei) {
    int e = blockIdx.x * blockDim.x + threadIdx.x;
    if (e < N_EDGES) atomicAdd(&g_cnt[load_dst(ei, e)], 1);
}

// ---------------- K3: proj1: p1 = x@Wl1.T (fp16), r1 = x@Wr1.T ----------
__global__ void __launch_bounds__(256) proj1_kernel(
        const float* __restrict__ x,
        const float* __restrict__ Wl1,
        const float* __restrict__ Wr1) {
    __shared__ float sWl[HID * IN_CH];
    __shared__ float sWr[HID * IN_CH];
    for (int t = threadIdx.x; t < HID * IN_CH; t += 256) {
        sWl[t] = Wl1[t];
        sWr[t] = Wr1[t];
    }
    __syncthreads();
    int i = blockIdx.x * 256 + threadIdx.x;
    if (i >= N_NODES) return;

    float xr[IN_CH];
    const float4* xp = reinterpret_cast<const float4*>(x + (size_t)i * IN_CH);
#pragma unroll
    for (int j = 0; j < IN_CH / 4; j++) {
        float4 v = __ldg(&xp[j]);
        xr[4 * j + 0] = v.x; xr[4 * j + 1] = v.y;
        xr[4 * j + 2] = v.z; xr[4 * j + 3] = v.w;
    }
    float pl[HID];
#pragma unroll
    for (int k = 0; k < HID; k++) {
        float a = 0.0f, b = 0.0f;
#pragma unroll
        for (int j = 0; j < IN_CH; j++) {
            a = fmaf(xr[j], sWl[k * IN_CH + j], a);
            b = fmaf(xr[j], sWr[k * IN_CH + j], b);
        }
        pl[k] = a;
        g_r1[i][k] = b;
    }
#pragma unroll
    for (int j = 0; j < 8; j++)
        g_p1h[i][j] = __floats2half2_rn(pl[2 * j], pl[2 * j + 1]);
}

// ---------------- K4-K6: shuffle-based scan of g_cnt -> g_rowptr ----------
__global__ void scanA_kernel() {
    int t = blockIdx.x * SCAN_B + threadIdx.x;
    int v = (t < N_NODES) ? g_cnt[t] : 0;
    int lane = threadIdx.x & 31, wid = threadIdx.x >> 5;
    int sv = v;
#pragma unroll
    for (int off = 1; off < 32; off <<= 1) {
        int n = __shfl_up_sync(0xffffffffu, sv, off);
        if (lane >= off) sv += n;
    }
    __shared__ int wsum[16];
    if (lane == 31) wsum[wid] = sv;
    __syncthreads();
    if (wid == 0 && lane < 16) {
        int w = wsum[lane], sw = w;
#pragma unroll
        for (int off = 1; off < 16; off <<= 1) {
            int n = __shfl_up_sync(0xffffu, sw, off);
            if (lane >= off) sw += n;
        }
        wsum[lane] = sw - w;  // exclusive
    }
    __syncthreads();
    int excl = sv - v + wsum[wid];
    if (t < N_NODES) g_rowptr[t] = excl;
    if (threadIdx.x == SCAN_B - 1) g_bsum[blockIdx.x] = excl + v;
}

__global__ void scanB_kernel() {
    int v = (threadIdx.x < NB) ? g_bsum[threadIdx.x] : 0;
    int lane = threadIdx.x & 31, wid = threadIdx.x >> 5;
    int sv = v;
#pragma unroll
    for (int off = 1; off < 32; off <<= 1) {
        int n = __shfl_up_sync(0xffffffffu, sv, off);
        if (lane >= off) sv += n;
    }
    __shared__ int wsum[8];
    if (lane == 31) wsum[wid] = sv;
    __syncthreads();
    if (wid == 0 && lane < 8) {
        int w = wsum[lane], sw = w;
#pragma unroll
        for (int off = 1; off < 8; off <<= 1) {
            int n = __shfl_up_sync(0xffu, sw, off);
            if (lane >= off) sw += n;
        }
        wsum[lane] = sw - w;
    }
    __syncthreads();
    if (threadIdx.x < NB) g_bsum[threadIdx.x] = sv - v + wsum[wid];  // exclusive
}

__global__ void scanC_kernel() {
    int t = blockIdx.x * blockDim.x + threadIdx.x;
    if (t < N_NODES) {
        int r = g_rowptr[t] + g_bsum[t / SCAN_B];
        g_rowptr[t] = r;
        g_woff[t] = r;
    }
    if (t == 0) g_rowptr[N_NODES] = N_EDGES;
}

// ---------------- K7: scatter src ids into CSR buckets ----------------
__global__ void __launch_bounds__(256) scatter_kernel(const void* __restrict__ ei) {
    int e = blockIdx.x * blockDim.x + threadIdx.x;
    if (e >= N_EDGES) return;
    int s, d;
    load_edge(ei, e, s, d);
    int pos = atomicAdd(&g_woff[d], 1);
    g_srcs[pos] = s;
}

// ---------------- K8: gather layer 1 (fp16 p1, 16 edges in flight) -------
// One warp per node. Lane layout: edge group g = lane>>1 (16 groups),
// c = lane&1 selects 16B half of the 32B fp16 row. Each lane does one
// LDG.128 per iteration -> warp retires 512B/instr across 16 rows.
// Mean degree 32 -> 2 iterations.
__global__ void __launch_bounds__(256) gather1_kernel(
        const float* __restrict__ b1,
        const float* __restrict__ Wl2,
        const float* __restrict__ Wr2) {
    int warp = (blockIdx.x * blockDim.x + threadIdx.x) >> 5;
    int lane = threadIdx.x & 31;
    if (warp >= N_NODES) return;
    int node = warp;
    int start = __ldg(&g_rowptr[node]);
    int end = __ldg(&g_rowptr[node + 1]);
    int g = lane >> 1;
    int c = lane & 1;

    float acc[8] = {0, 0, 0, 0, 0, 0, 0, 0};
    for (int e = start + g; e < end; e += 16) {
        int s = __ldg(&g_srcs[e]);
        int4 v = __ldg(reinterpret_cast<const int4*>(&g_p1h[s][0]) + c);
        float2 f0 = __half22float2(*(__half2*)&v.x);
        float2 f1 = __half22float2(*(__half2*)&v.y);
        float2 f2 = __half22float2(*(__half2*)&v.z);
        float2 f3 = __half22float2(*(__half2*)&v.w);
        acc[0] += f0.x; acc[1] += f0.y;
        acc[2] += f1.x; acc[3] += f1.y;
        acc[4] += f2.x; acc[5] += f2.y;
        acc[6] += f3.x; acc[7] += f3.y;
    }
    // fold 16 edge groups -> lanes 0 (c=0: ch0-7) and 1 (c=1: ch8-15)
#pragma unroll
    for (int off = 16; off >= 2; off >>= 1) {
#pragma unroll
        for (int j = 0; j < 8; j++)
            acc[j] += __shfl_down_sync(0xffffffffu, acc[j], off);
    }

    // epilogue on all lanes (channel index masked in-range; only lane 0 writes)
    float dinv = 1.0f / fmaxf((float)(end - start), 1.0f);
    float p2 = 0.0f, r2 = 0.0f;
    int cbase = (lane & 1) * 8;
#pragma unroll
    for (int j = 0; j < 8; j++) {
        int ch = cbase + j;
        float h = fmaf(acc[j], dinv, __ldg(&b1[ch]) + g_r1[node][ch]);
        h = fmaxf(h, 0.0f);
        p2 = fmaf(h, __ldg(&Wl2[ch]), p2);
        r2 = fmaf(h, __ldg(&Wr2[ch]), r2);
    }
    p2 += __shfl_down_sync(0xffffffffu, p2, 1);
    r2 += __shfl_down_sync(0xffffffffu, r2, 1);
    if (lane == 0) {
        g_p2[node] = p2;
        g_r2[node] = r2;
    }
}

// ---------------- K9: gather layer 2 (fused final epilogue) ----------------
__global__ void __launch_bounds__(256) gather2_kernel(
        const float* __restrict__ b2,
        float* __restrict__ out) {
    int warp = (blockIdx.x * blockDim.x + threadIdx.x) >> 5;
    int lane = threadIdx.x & 31;
    if (warp >= N_NODES) return;
    int start = __ldg(&g_rowptr[warp]);
    int end = __ldg(&g_rowptr[warp + 1]);
    float acc = 0.0f;
    for (int e = start + lane; e < end; e += 32)
        acc += __ldg(&g_p2[__ldg(&g_srcs[e])]);
#pragma unroll
    for (int o = 16; o; o >>= 1)
        acc += __shfl_down_sync(0xffffffffu, acc, o);
    if (lane == 0) {
        float dinv = 1.0f / fmaxf((float)(end - start), 1.0f);
        out[warp] = fmaf(acc, dinv, __ldg(&b2[0]) + g_r2[warp]);
    }
}

// ---------------- launch ----------------
extern "C" void kernel_launch(void* const* d_in, const int* in_sizes, int n_in,
                              void* d_out, int out_size) {
    const float* x   = (const float*)d_in[0];
    const void*  ei  = d_in[1];
    const float* Wl1 = (const float*)d_in[2];
    const float* Wr1 = (const float*)d_in[3];
    const float* b1  = (const float*)d_in[4];
    const float* Wl2 = (const float*)d_in[5];
    const float* Wr2 = (const float*)d_in[6];
    const float* b2  = (const float*)d_in[7];
    float* out = (float*)d_out;

    const int T = 256;
    const int WG = (N_NODES * 32 + T - 1) / T;  // 12500 (warp per node)

    init_kernel<<<NG, T>>>((const int*)ei);
    hist_kernel<<<EG, T>>>(ei);
    proj1_kernel<<<NG, T>>>(x, Wl1, Wr1);
    scanA_kernel<<<NB, SCAN_B>>>();
    scanB_kernel<<<1, 256>>>();
    scanC_kernel<<<NG, T>>>();
    scatter_kernel<<<EG, T>>>(ei);
    gather1_kernel<<<WG, T>>>(b1, Wl2, Wr2);
    gather2_kernel<<<WG, T>>>(b2, out);
}